// round 14
// baseline (speedup 1.0000x reference)
#include <cuda_runtime.h>
#include <cstdint>

// ImageWarpingLayer: out = bilinear_sample(image, grid + flow)
// image: [B=16, H=512, W=512, C=8] f32   flow: [B, H, W, 2] f32 (dy, dx)
// TF dense_image_warp semantics: floor clamped to [0, size-2],
// alpha = clip(q - floor, 0, 1).
//
// 128-thread blocks, work-unit = (pixel, float4-half-of-C), 2 units/thread,
// LDG.128 gathers with L1 policy hints (image: evict_last, flow:
// evict_first). Single-phase: both units computed and staged back-to-back
// (no barrier between gather batches), then ONE __syncthreads + ONE 4KB
// cp.async.bulk (TMA) store + wait_group.read.

#define Bn 16
#define Hn 512
#define Wn 512
#define Cn 8

#define THREADS 128
#define UNITS_PER_BLOCK 256             // 2 units per thread
#define HALF_UNITS_BLK  128
#define TOTAL_UNITS (Bn * Hn * Wn * 2)  // 8388608

#define ROW_BYTES (Wn * Cn * 4)         // 16384 bytes per image row
#define PIX_BYTES (Cn * 4)              // 32 bytes per pixel

__device__ __forceinline__ uint32_t smem_u32(const void* p) {
    uint32_t a;
    asm("{ .reg .u64 t; cvta.to.shared.u64 t, %1; cvt.u32.u64 %0, t; }"
        : "=r"(a) : "l"(p));
    return a;
}

__device__ __forceinline__ float4 ldg_el(const void* p) {
    float4 v;
    asm("ld.global.nc.L1::evict_last.v4.f32 {%0,%1,%2,%3}, [%4];"
        : "=f"(v.x), "=f"(v.y), "=f"(v.z), "=f"(v.w) : "l"(p));
    return v;
}

__device__ __forceinline__ float2 ldg_ef2(const void* p) {
    float2 v;
    asm("ld.global.nc.L1::evict_first.v2.f32 {%0,%1}, [%2];"
        : "=f"(v.x), "=f"(v.y) : "l"(p));
    return v;
}

__global__ __launch_bounds__(THREADS, 16)
void warp_kernel(const char* __restrict__ image,
                 const float* __restrict__ flow,
                 float* __restrict__ out)
{
    __shared__ __align__(16) float4 buf[UNITS_PER_BLOCK];  // 4 KB

    const int base = blockIdx.x * UNITS_PER_BLOCK;
    const int t    = threadIdx.x;

    // ---- front-batched flow loads for both halves (streaming hint) ----
    float2 f[2];
#pragma unroll
    for (int k = 0; k < 2; k++) {
        const int pix = (base + t + k * HALF_UNITS_BLK) >> 1;
        f[k] = ldg_ef2(reinterpret_cast<const float2*>(flow) + pix);
    }

#pragma unroll
    for (int k = 0; k < 2; k++) {
        const int slot = t + k * HALF_UNITS_BLK;
        const int uid  = base + slot;

        const int pix  = uid >> 1;      // pixel id ((b*H + y)*W + x)
        const int half = uid & 1;       // which float4 half of C

        const int x = pix & (Wn - 1);
        const int y = (pix >> 9) & (Hn - 1);
        const int b = pix >> 18;

        const float qy = (float)y + f[k].x;
        const float qx = (float)x + f[k].y;

        const float fy = fminf(fmaxf(floorf(qy), 0.0f), (float)(Hn - 2));
        const float fx = fminf(fmaxf(floorf(qx), 0.0f), (float)(Wn - 2));
        const float ay = fminf(fmaxf(qy - fy, 0.0f), 1.0f);
        const float ax = fminf(fmaxf(qx - fx, 0.0f), 1.0f);

        const int iy = (int)fy;
        const int ix = (int)fx;

        // 32-bit byte offsets (image spans 2^27 bytes)
        const uint32_t top = (uint32_t)(b * Hn + iy) * ROW_BYTES
                           + (uint32_t)ix * PIX_BYTES + (uint32_t)(half << 4);
        const uint32_t bot = top + ROW_BYTES;

        const float4 tl = ldg_el(image + top);
        const float4 tr = ldg_el(image + top + PIX_BYTES);
        const float4 bl = ldg_el(image + bot);
        const float4 br = ldg_el(image + bot + PIX_BYTES);

        float4 o;
        float tt, bo;
        tt  = fmaf(ax, tr.x - tl.x, tl.x);
        bo  = fmaf(ax, br.x - bl.x, bl.x);
        o.x = fmaf(ay, bo - tt, tt);
        tt  = fmaf(ax, tr.y - tl.y, tl.y);
        bo  = fmaf(ax, br.y - bl.y, bl.y);
        o.y = fmaf(ay, bo - tt, tt);
        tt  = fmaf(ax, tr.z - tl.z, tl.z);
        bo  = fmaf(ax, br.z - bl.z, bl.z);
        o.z = fmaf(ay, bo - tt, tt);
        tt  = fmaf(ax, tr.w - tl.w, tl.w);
        bo  = fmaf(ax, br.w - bl.w, bl.w);
        o.w = fmaf(ay, bo - tt, tt);

        buf[slot] = o;  // STS.128, conflict-free; no barrier between halves
    }

    // Single barrier + single 4KB TMA store for the whole block's tile.
    __syncthreads();
    if (t == 0) {
        asm volatile("fence.proxy.async.shared::cta;" ::: "memory");
        const uint32_t s = smem_u32(buf);
        float* g = out + (long)base * 4;  // 4 floats per unit
        asm volatile(
            "cp.async.bulk.global.shared::cta.bulk_group [%0], [%1], %2;"
            :: "l"(g), "r"(s), "n"(UNITS_PER_BLOCK * 16) : "memory");
        asm volatile("cp.async.bulk.commit_group;" ::: "memory");
        asm volatile("cp.async.bulk.wait_group.read 0;" ::: "memory");
    }
}

extern "C" void kernel_launch(void* const* d_in, const int* in_sizes, int n_in,
                              void* d_out, int out_size)
{
    const char*  image = (const char*)d_in[0];
    const float* flow  = (const float*)d_in[1];
    float* out = (float*)d_out;

    const int blocks = TOTAL_UNITS / UNITS_PER_BLOCK; // 32768
    warp_kernel<<<blocks, THREADS>>>(image, flow, out);
}

// round 15
// speedup vs baseline: 1.0016x; 1.0016x over previous
#include <cuda_runtime.h>
#include <cstdint>

// ImageWarpingLayer: out = bilinear_sample(image, grid + flow)
// image: [B=16, H=512, W=512, C=8] f32   flow: [B, H, W, 2] f32 (dy, dx)
// TF dense_image_warp semantics: floor clamped to [0, size-2],
// alpha = clip(q - floor, 0, 1).
//
// R13 config (128-thread blocks, 2 units/thread, LDG.128 gathers, split
// SMEM-staged TMA bulk stores, L1 policy hints) + L2::256B prefetch on all
// global loads to cut L2->DRAM fill transactions (miss-path relief).

#define Bn 16
#define Hn 512
#define Wn 512
#define Cn 8

#define THREADS 128
#define UNITS_PER_BLOCK 256             // 2 units per thread
#define HALF_UNITS_BLK  128
#define TOTAL_UNITS (Bn * Hn * Wn * 2)  // 8388608

#define ROW_BYTES (Wn * Cn * 4)         // 16384 bytes per image row
#define PIX_BYTES (Cn * 4)              // 32 bytes per pixel

__device__ __forceinline__ uint32_t smem_u32(const void* p) {
    uint32_t a;
    asm("{ .reg .u64 t; cvta.to.shared.u64 t, %1; cvt.u32.u64 %0, t; }"
        : "=r"(a) : "l"(p));
    return a;
}

__device__ __forceinline__ float4 ldg_el(const void* p) {
    float4 v;
    asm("ld.global.nc.L1::evict_last.L2::256B.v4.f32 {%0,%1,%2,%3}, [%4];"
        : "=f"(v.x), "=f"(v.y), "=f"(v.z), "=f"(v.w) : "l"(p));
    return v;
}

__device__ __forceinline__ float2 ldg_ef2(const void* p) {
    float2 v;
    asm("ld.global.nc.L1::evict_first.L2::256B.v2.f32 {%0,%1}, [%2];"
        : "=f"(v.x), "=f"(v.y) : "l"(p));
    return v;
}

__global__ __launch_bounds__(THREADS, 16)
void warp_kernel(const char* __restrict__ image,
                 const float* __restrict__ flow,
                 float* __restrict__ out)
{
    __shared__ __align__(16) float4 buf[UNITS_PER_BLOCK];  // 4 KB

    const int base = blockIdx.x * UNITS_PER_BLOCK;
    const int t    = threadIdx.x;

    // ---- front-batched flow loads for both halves (streaming hint) ----
    float2 f[2];
#pragma unroll
    for (int k = 0; k < 2; k++) {
        const int pix = (base + t + k * HALF_UNITS_BLK) >> 1;
        f[k] = ldg_ef2(reinterpret_cast<const float2*>(flow) + pix);
    }

#pragma unroll
    for (int k = 0; k < 2; k++) {
        const int slot = t + k * HALF_UNITS_BLK;
        const int uid  = base + slot;

        const int pix  = uid >> 1;      // pixel id ((b*H + y)*W + x)
        const int half = uid & 1;       // which float4 half of C

        const int x = pix & (Wn - 1);
        const int y = (pix >> 9) & (Hn - 1);
        const int b = pix >> 18;

        const float qy = (float)y + f[k].x;
        const float qx = (float)x + f[k].y;

        const float fy = fminf(fmaxf(floorf(qy), 0.0f), (float)(Hn - 2));
        const float fx = fminf(fmaxf(floorf(qx), 0.0f), (float)(Wn - 2));
        const float ay = fminf(fmaxf(qy - fy, 0.0f), 1.0f);
        const float ax = fminf(fmaxf(qx - fx, 0.0f), 1.0f);

        const int iy = (int)fy;
        const int ix = (int)fx;

        // 32-bit byte offsets (image spans 2^27 bytes)
        const uint32_t top = (uint32_t)(b * Hn + iy) * ROW_BYTES
                           + (uint32_t)ix * PIX_BYTES + (uint32_t)(half << 4);
        const uint32_t bot = top + ROW_BYTES;

        const float4 tl = ldg_el(image + top);
        const float4 tr = ldg_el(image + top + PIX_BYTES);
        const float4 bl = ldg_el(image + bot);
        const float4 br = ldg_el(image + bot + PIX_BYTES);

        float4 o;
        float tt, bo;
        tt  = fmaf(ax, tr.x - tl.x, tl.x);
        bo  = fmaf(ax, br.x - bl.x, bl.x);
        o.x = fmaf(ay, bo - tt, tt);
        tt  = fmaf(ax, tr.y - tl.y, tl.y);
        bo  = fmaf(ax, br.y - bl.y, bl.y);
        o.y = fmaf(ay, bo - tt, tt);
        tt  = fmaf(ax, tr.z - tl.z, tl.z);
        bo  = fmaf(ax, br.z - bl.z, bl.z);
        o.z = fmaf(ay, bo - tt, tt);
        tt  = fmaf(ax, tr.w - tl.w, tl.w);
        bo  = fmaf(ax, br.w - bl.w, bl.w);
        o.w = fmaf(ay, bo - tt, tt);

        buf[slot] = o;  // STS.128, conflict-free

        // After half k is staged, kick its 2KB TMA store; the k=0 store
        // drains while the block computes k=1.
        __syncthreads();
        if (t == 0) {
            asm volatile("fence.proxy.async.shared::cta;" ::: "memory");
            const uint32_t s = smem_u32(buf) + k * (HALF_UNITS_BLK * 16);
            float* g = out + (long)(base + k * HALF_UNITS_BLK) * 4;
            asm volatile(
                "cp.async.bulk.global.shared::cta.bulk_group [%0], [%1], %2;"
                :: "l"(g), "r"(s), "n"(HALF_UNITS_BLK * 16) : "memory");
            asm volatile("cp.async.bulk.commit_group;" ::: "memory");
        }
    }

    // t==0 issued the TMAs; ensure SMEM fully read before block exit.
    if (t == 0) {
        asm volatile("cp.async.bulk.wait_group.read 0;" ::: "memory");
    }
}

extern "C" void kernel_launch(void* const* d_in, const int* in_sizes, int n_in,
                              void* d_out, int out_size)
{
    const char*  image = (const char*)d_in[0];
    const float* flow  = (const float*)d_in[1];
    float* out = (float*)d_out;

    const int blocks = TOTAL_UNITS / UNITS_PER_BLOCK; // 32768
    warp_kernel<<<blocks, THREADS>>>(image, flow, out);
}